// round 14
// baseline (speedup 1.0000x reference)
#include <cuda_runtime.h>
#include <cuda_bf16.h>
#include <math.h>
#include <stdint.h>

#define Bc 8
#define Sc 1024
#define Hc 8
#define Dc 64
#define DMc 512
#define NTOT (Bc*Hc*Sc*Dc)   // 4,194,304

// ---- scratch (device globals; no allocations allowed) ----
__device__ float g_gate[NTOT];   // (B,H,S,D) fp32
__device__ float g_attn[NTOT];   // (B,S,H,D) fp32
__device__ float g_mean[Bc*8];
__device__ float g_rstd[Bc*8];

// bf16 hi/lo attention operands, (B,H,S,D)
__device__ __align__(16) __nv_bfloat16 g_q1h[NTOT], g_q1l[NTOT];
__device__ __align__(16) __nv_bfloat16 g_q2h[NTOT], g_q2l[NTOT];
__device__ __align__(16) __nv_bfloat16 g_k1h[NTOT], g_k1l[NTOT];
__device__ __align__(16) __nv_bfloat16 g_k2h[NTOT], g_k2l[NTOT];
__device__ __align__(16) __nv_bfloat16 g_vh[NTOT],  g_vl[NTOT];

// bf16 hi/lo split operands for tensor-core projection GEMMs
__device__ __align__(16) __nv_bfloat16 g_Ahi[3][8192*512];
__device__ __align__(16) __nv_bfloat16 g_Alo[3][8192*512];
__device__ __align__(16) __nv_bfloat16 g_Whi[3072*512];   // W^T, [N][K] layout
__device__ __align__(16) __nv_bfloat16 g_Wlo[3072*512];

// ============================================================
// helpers
// ============================================================
__device__ __forceinline__ uint32_t smem_u32(const void* p) {
    uint32_t a;
    asm("{ .reg .u64 t; cvta.to.shared.u64 t, %1; cvt.u32.u64 %0, t; }" : "=r"(a) : "l"(p));
    return a;
}
__device__ __forceinline__ void ldsm_x4(uint32_t* r, uint32_t addr) {
    asm volatile("ldmatrix.sync.aligned.m8n8.x4.shared.b16 {%0,%1,%2,%3}, [%4];"
                 : "=r"(r[0]), "=r"(r[1]), "=r"(r[2]), "=r"(r[3]) : "r"(addr));
}
__device__ __forceinline__ void ldsm_x4t(uint32_t* r, uint32_t addr) {
    asm volatile("ldmatrix.sync.aligned.m8n8.x4.trans.shared.b16 {%0,%1,%2,%3}, [%4];"
                 : "=r"(r[0]), "=r"(r[1]), "=r"(r[2]), "=r"(r[3]) : "r"(addr));
}
__device__ __forceinline__ void mma16816(float* c, const uint32_t* a, const uint32_t* b) {
    asm volatile("mma.sync.aligned.m16n8k16.row.col.f32.bf16.bf16.f32 "
                 "{%0,%1,%2,%3}, {%4,%5,%6,%7}, {%8,%9}, {%0,%1,%2,%3};"
                 : "+f"(c[0]), "+f"(c[1]), "+f"(c[2]), "+f"(c[3])
                 : "r"(a[0]), "r"(a[1]), "r"(a[2]), "r"(a[3]), "r"(b[0]), "r"(b[1]));
}
__device__ __forceinline__ void cp_async16(uint32_t sa, const void* g) {
    asm volatile("cp.async.cg.shared.global [%0], [%1], 16;" :: "r"(sa), "l"(g) : "memory");
}
__device__ __forceinline__ uint32_t cvt2bf(float a, float b) {
    uint32_t r;
    asm("cvt.rn.bf16x2.f32 %0, %1, %2;" : "=r"(r) : "f"(b), "f"(a));
    return r;
}
__device__ __forceinline__ void split2bf(float a, float b, uint32_t& ph, uint32_t& pl) {
    ph = cvt2bf(a, b);
    float ha = __uint_as_float(ph << 16);
    float hb = __uint_as_float(ph & 0xFFFF0000u);
    pl = cvt2bf(a - ha, b - hb);
}
#define SW128(off) ((off) ^ (((off) >> 3) & 0x70))
#define SC2G 0.18033688011112042f   // 0.125 * log2(e)

// ============================================================
// Fused conversion kernels
// ============================================================
__global__ __launch_bounds__(256)
void convA_all(const float* __restrict__ Xq, const float* __restrict__ Xk,
               const float* __restrict__ Xv)
{
    const int which = blockIdx.x >> 12;
    const float* X = (which == 0) ? Xq : (which == 1) ? Xk : Xv;
    int i = ((blockIdx.x & 4095) * 256 + threadIdx.x) * 4;
    float4 x = *(const float4*)(X + i);
    uint32_t h01, l01, h23, l23;
    split2bf(x.x, x.y, h01, l01);
    split2bf(x.z, x.w, h23, l23);
    uint2* ph = (uint2*)(&g_Ahi[which][i]);
    uint2* pl = (uint2*)(&g_Alo[which][i]);
    *ph = make_uint2(h01, h23);
    *pl = make_uint2(l01, l23);
}

__global__ __launch_bounds__(256)
void convW_all(const float* __restrict__ Wq, const float* __restrict__ Wk,
               const float* __restrict__ Wv)
{
    __shared__ float t[32][33];
    int by = blockIdx.y;
    const float* W; int N; int off;
    if (by < 48)      { W = Wq; N = 1536; off = 0;           }
    else if (by < 80) { W = Wk; N = 1024; off = 1536*512; by -= 48; }
    else              { W = Wv; N = 512;  off = 2560*512; by -= 80; }
    const int k0 = blockIdx.x * 32;
    const int n0 = by * 32;
    const int tx = threadIdx.x & 31;
    const int ty = threadIdx.x >> 5;
    #pragma unroll
    for (int i = ty; i < 32; i += 8)
        t[i][tx] = W[(size_t)(k0 + i) * N + n0 + tx];
    __syncthreads();
    #pragma unroll
    for (int i = ty; i < 32; i += 8) {
        float x = t[tx][i];
        __nv_bfloat16 h = __float2bfloat16(x);
        size_t idx = (size_t)off + (size_t)(n0 + i) * 512 + k0 + tx;
        g_Whi[idx] = h;
        g_Wlo[idx] = __float2bfloat16(x - __bfloat162float(h));
    }
}

// ============================================================
// Merged HMMA projection GEMM (bf16x3), 3-stage cp.async ring,
// ONE barrier per K-chunk. q1/q2 pre-scaled by 0.125*log2e.
// ============================================================
#define GEMM_SMEM 98304   // 3 stages x (A 16KB + B 16KB)

__global__ __launch_bounds__(256, 2)
void gemm_hmma(const float* __restrict__ bq, const float* __restrict__ bk,
               const float* __restrict__ bv)
{
    extern __shared__ __align__(1024) char smem[];
    const uint32_t sbase = smem_u32(smem);
    const int tid = threadIdx.x;
    const int lane = tid & 31;
    const int wid = tid >> 5;
    const int wm = (wid & 1) * 64;
    const int wn = (wid >> 1) * 32;

    const int m0 = blockIdx.x * 128;
    int by = blockIdx.y;
    int which, woff, perHead, mode; const float* bias;
    if (by < 12)      { which = 0; woff = 0;        bias = bq; perHead = 192; mode = 0; }
    else if (by < 20) { which = 1; woff = 1536*512; bias = bk; perHead = 128; mode = 1; by -= 12; }
    else              { which = 2; woff = 2560*512; bias = bv; perHead = 64;  mode = 2; by -= 20; }
    const int n0 = by * 128;

    const __nv_bfloat16* Ahi = g_Ahi[which];
    const __nv_bfloat16* Alo = g_Alo[which];
    const __nv_bfloat16* Whi = g_Whi + (size_t)woff;
    const __nv_bfloat16* Wlo = g_Wlo + (size_t)woff;

    float C[4][4][4];
    #pragma unroll
    for (int i = 0; i < 4; i++)
        #pragma unroll
        for (int j = 0; j < 4; j++)
            #pragma unroll
            for (int c = 0; c < 4; c++) C[i][j][c] = 0.0f;

    const int lrow = tid >> 1;
    const int lu   = (tid & 1) * 2;
    auto load_chunk = [&](int c, int s) {
        const int kc = c * 32;
        const uint32_t ab = (uint32_t)s * 32768u;
        const uint32_t bb = ab + 16384u;
        #pragma unroll
        for (int e = 0; e < 2; e++) {
            int u = lu + e;
            uint32_t dh = SW128((uint32_t)(lrow * 128 + u * 16));
            uint32_t dl = SW128((uint32_t)(lrow * 128 + 64 + u * 16));
            cp_async16(sbase + ab + dh, Ahi + (size_t)(m0 + lrow) * 512 + kc + u * 8);
            cp_async16(sbase + ab + dl, Alo + (size_t)(m0 + lrow) * 512 + kc + u * 8);
            cp_async16(sbase + bb + dh, Whi + (size_t)(n0 + lrow) * 512 + kc + u * 8);
            cp_async16(sbase + bb + dl, Wlo + (size_t)(n0 + lrow) * 512 + kc + u * 8);
        }
        asm volatile("cp.async.commit_group;" ::: "memory");
    };

    // prologue: 2-chunk lookahead
    load_chunk(0, 0);
    load_chunk(1, 1);

    int stage = 0;   // stage of chunk c
    for (int c = 0; c < 16; c++) {
        if (c < 15) asm volatile("cp.async.wait_group 1;" ::: "memory");
        else        asm volatile("cp.async.wait_group 0;" ::: "memory");
        __syncthreads();   // single barrier: data visible + prior reads of (c+2)%3 done
        if (c < 14) {
            int ns = stage + 2; if (ns >= 3) ns -= 3;
            load_chunk(c + 2, ns);
        }

        const uint32_t ab = (uint32_t)stage * 32768u;
        const uint32_t bb = ab + 16384u;
        #pragma unroll
        for (int ks = 0; ks < 2; ks++) {
            uint32_t ah[4][4], al[4][4];
            #pragma unroll
            for (int mi = 0; mi < 4; mi++) {
                uint32_t base = (uint32_t)((wm + mi * 16 + (lane & 15)) * 128 + ks * 32 + (lane >> 4) * 16);
                ldsm_x4(ah[mi], sbase + ab + SW128(base));
                ldsm_x4(al[mi], sbase + ab + SW128(base + 64));
            }
            uint32_t bh[2][4], bl[2][4];
            #pragma unroll
            for (int n2 = 0; n2 < 2; n2++) {
                uint32_t base = (uint32_t)((wn + n2 * 16 + ((lane >> 4) & 1) * 8 + (lane & 7)) * 128
                                           + ks * 32 + ((lane >> 3) & 1) * 16);
                ldsm_x4(bh[n2], sbase + bb + SW128(base));
                ldsm_x4(bl[n2], sbase + bb + SW128(base + 64));
            }
            #pragma unroll
            for (int mi = 0; mi < 4; mi++)
                #pragma unroll
                for (int n2 = 0; n2 < 2; n2++)
                    #pragma unroll
                    for (int e = 0; e < 2; e++) {
                        mma16816(C[mi][2*n2+e], ah[mi], bh[n2] + 2*e);
                        mma16816(C[mi][2*n2+e], ah[mi], bl[n2] + 2*e);
                        mma16816(C[mi][2*n2+e], al[mi], bh[n2] + 2*e);
                    }
        }
        stage++; if (stage >= 3) stage = 0;
    }

    #pragma unroll
    for (int ni = 0; ni < 4; ni++) {
        const int ng = n0 + wn + ni * 8 + (lane & 3) * 2;
        const int hh  = ng / perHead;
        const int r   = ng % perHead;
        const int seg = r >> 6;
        const int d   = r & 63;
        const float bx = bias[ng], by2 = bias[ng + 1];
        __nv_bfloat16 *ph = 0, *pl = 0; float* pf = 0;
        if (mode == 0) {
            if (seg == 0)      { ph = g_q1h; pl = g_q1l; }
            else if (seg == 1) { ph = g_q2h; pl = g_q2l; }
            else               { pf = g_gate; }
        } else if (mode == 1) {
            if (seg == 0) { ph = g_k1h; pl = g_k1l; }
            else          { ph = g_k2h; pl = g_k2l; }
        } else { ph = g_vh; pl = g_vl; }
        const float qs = (mode == 0 && seg != 2) ? SC2G : 1.0f;
        #pragma unroll
        for (int mi = 0; mi < 4; mi++) {
            #pragma unroll
            for (int half = 0; half < 2; half++) {
                int m = m0 + wm + mi * 16 + (lane >> 2) + half * 8;
                int bb2 = m >> 10, s = m & 1023;
                size_t idx = (size_t)((bb2 * Hc + hh) * Sc + s) * Dc + d;
                float v0 = (C[mi][ni][half * 2 + 0] + bx)  * qs;
                float v1 = (C[mi][ni][half * 2 + 1] + by2) * qs;
                if (pf) {
                    *(float2*)(pf + idx) = make_float2(v0, v1);
                } else {
                    uint32_t hp, lp;
                    split2bf(v0, v1, hp, lp);
                    *(uint32_t*)(ph + idx) = hp;
                    *(uint32_t*)(pl + idx) = lp;
                }
            }
        }
    }
}

// ============================================================
// HMMA flash attention v7 (unchanged R13 — 253us):
// no online max, unnormalized P, end-of-loop l reduction.
// ============================================================
#define AQ1H 0
#define AQ1L 8192
#define AQ2H 16384
#define AQ2L 24576
#define AKV0 32768
#define KVSZ 24576
#define AML  81920
#define ACMB 32768
#define ATTN_SMEM 83968

__global__ __launch_bounds__(256, 2)
void attn_hmma(const float* __restrict__ lam_p)
{
    extern __shared__ __align__(1024) char smem[];
    const uint32_t sb = smem_u32(smem);
    const int tid = threadIdx.x;
    const int lane = tid & 31;
    const int w = tid >> 5;
    const int wm = (w & 3) * 16;
    const int half = w >> 2;
    const int kh = half * 16;

    const int q0 = blockIdx.x * 64;
    const int h = blockIdx.y;
    const int b = blockIdx.z;
    const size_t ho = (size_t)(b * Hc + h) * Sc * Dc;

    const __nv_bfloat16* src[6] = { g_k1h + ho, g_k1l + ho, g_k2h + ho,
                                    g_k2l + ho, g_vh + ho, g_vl + ho };

    {
        const __nv_bfloat16* qs[4] = { g_q1h + ho + (size_t)q0 * Dc, g_q1l + ho + (size_t)q0 * Dc,
                                       g_q2h + ho + (size_t)q0 * Dc, g_q2l + ho + (size_t)q0 * Dc };
        #pragma unroll
        for (int t = 0; t < 4; t++)
            #pragma unroll
            for (int i = 0; i < 2; i++) {
                int idx = tid + 256 * i;
                int row = idx >> 3, u = idx & 7;
                *(uint4*)(smem + t * 8192 + SW128((uint32_t)(row * 128 + u * 16))) =
                    *(const uint4*)(qs[t] + row * 64 + u * 8);
            }
    }
    {
        int row = tid >> 3, u = tid & 7;
        uint32_t soff = SW128((uint32_t)(row * 128 + u * 16));
        #pragma unroll
        for (int t = 0; t < 6; t++)
            cp_async16(sb + AKV0 + t * 4096 + soff, src[t] + (size_t)row * 64 + u * 8);
        asm volatile("cp.async.commit_group;" ::: "memory");
    }

    float O1[8][4], O2[8][4];
    #pragma unroll
    for (int nd = 0; nd < 8; nd++)
        #pragma unroll
        for (int c = 0; c < 4; c++) { O1[nd][c] = 0.0f; O2[nd][c] = 0.0f; }
    float L1a = 0.0f, L1b = 0.0f, L2a = 0.0f, L2b = 0.0f;

    const int r0 = wm + (lane >> 2);

    for (int kt = 0; kt < 32; kt++) {
        const uint32_t bufb = AKV0 + (uint32_t)(kt & 1) * KVSZ;
        asm volatile("cp.async.wait_group 0;" ::: "memory");
        __syncthreads();

        float s1[2][4], s2[2][4];
        #pragma unroll
        for (int ni = 0; ni < 2; ni++)
            #pragma unroll
            for (int c = 0; c < 4; c++) { s1[ni][c] = 0.0f; s2[ni][c] = 0.0f; }

        const uint32_t brow = (uint32_t)(kh + ((lane >> 4) & 1) * 8 + (lane & 7));
        #pragma unroll
        for (int ks = 0; ks < 4; ks++) {
            uint32_t aoff = SW128((uint32_t)((wm + (lane & 15)) * 128 + ks * 32 + (lane >> 4) * 16));
            uint32_t a1h[4], a1l[4], a2h[4], a2l[4];
            ldsm_x4(a1h, sb + AQ1H + aoff); ldsm_x4(a1l, sb + AQ1L + aoff);
            ldsm_x4(a2h, sb + AQ2H + aoff); ldsm_x4(a2l, sb + AQ2L + aoff);
            uint32_t boff = SW128(brow * 128 + (uint32_t)(ks * 32 + ((lane >> 3) & 1) * 16));
            uint32_t b1h[4], b1l[4], b2h[4], b2l[4];
            ldsm_x4(b1h, sb + bufb + 0     + boff);
            ldsm_x4(b1l, sb + bufb + 4096  + boff);
            ldsm_x4(b2h, sb + bufb + 8192  + boff);
            ldsm_x4(b2l, sb + bufb + 12288 + boff);
            #pragma unroll
            for (int ni = 0; ni < 2; ni++) {
                mma16816(s1[ni], a1h, b1h + 2*ni); mma16816(s1[ni], a1h, b1l + 2*ni); mma16816(s1[ni], a1l, b1h + 2*ni);
                mma16816(s2[ni], a2h, b2h + 2*ni); mma16816(s2[ni], a2h, b2l + 2*ni); mma16816(s2[ni], a2l, b2h + 2*ni);
            }
        }

        if (kt < 31) {
            const uint32_t nb = AKV0 + (uint32_t)((kt + 1) & 1) * KVSZ;
            int row = tid >> 3, u = tid & 7;
            uint32_t soff = SW128((uint32_t)(row * 128 + u * 16));
            #pragma unroll
            for (int t = 0; t < 6; t++)
                cp_async16(sb + nb + t * 4096 + soff,
                           src[t] + (size_t)((kt + 1) * 32 + row) * 64 + u * 8);
            asm volatile("cp.async.commit_group;" ::: "memory");
        }

        uint32_t p1h[4], p1l[4], p2h[4], p2l[4];
        #pragma unroll
        for (int e = 0; e < 2; e++) {
            float q0v = exp2f(s1[e][0]);
            float q1v = exp2f(s1[e][1]);
            float q2v = exp2f(s1[e][2]);
            float q3v = exp2f(s1[e][3]);
            L1a += q0v + q1v; L1b += q2v + q3v;
            split2bf(q0v, q1v, p1h[2 * e],     p1l[2 * e]);
            split2bf(q2v, q3v, p1h[2 * e + 1], p1l[2 * e + 1]);

            q0v = exp2f(s2[e][0]);
            q1v = exp2f(s2[e][1]);
            q2v = exp2f(s2[e][2]);
            q3v = exp2f(s2[e][3]);
            L2a += q0v + q1v; L2b += q2v + q3v;
            split2bf(q0v, q1v, p2h[2 * e],     p2l[2 * e]);
            split2bf(q2v, q3v, p2h[2 * e + 1], p2l[2 * e + 1]);
        }

        #pragma unroll
        for (int np = 0; np < 4; np++) {
            uint32_t voff = SW128((uint32_t)((kh + (lane & 15)) * 128 +
                                             (np * 2 + ((lane >> 4) & 1)) * 16));
            uint32_t vh4[4], vl4[4];
            ldsm_x4t(vh4, sb + bufb + 16384u + voff);
            ldsm_x4t(vl4, sb + bufb + 20480u + voff);
            #pragma unroll
            for (int e = 0; e < 2; e++) {
                mma16816(O1[2*np+e], p1h, vh4 + 2*e); mma16816(O1[2*np+e], p1h, vl4 + 2*e); mma16816(O1[2*np+e], p1l, vh4 + 2*e);
                mma16816(O2[2*np+e], p2h, vh4 + 2*e); mma16816(O2[2*np+e], p2h, vl4 + 2*e); mma16816(O2[2*np+e], p2l, vh4 + 2*e);
            }
        }
    }

    L1a += __shfl_xor_sync(0xffffffffu, L1a, 1);
    L1a += __shfl_xor_sync(0xffffffffu, L1a, 2);
    L1b += __shfl_xor_sync(0xffffffffu, L1b, 1);
    L1b += __shfl_xor_sync(0xffffffffu, L1b, 2);
    L2a += __shfl_xor_sync(0xffffffffu, L2a, 1);
    L2a += __shfl_xor_sync(0xffffffffu, L2a, 2);
    L2b += __shfl_xor_sync(0xffffffffu, L2b, 1);
    L2b += __shfl_xor_sync(0xffffffffu, L2b, 2);
    __syncthreads();

    float* cO1 = (float*)(smem + ACMB);
    float* cO2 = cO1 + 64 * 66;
    float* sl1 = (float*)(smem + AML);
    float* sl2 = sl1 + 64;
    const float lam = lam_p[0];

    if (half == 1) {
        #pragma unroll
        for (int nd = 0; nd < 8; nd++) {
            int cc = nd * 8 + (lane & 3) * 2;
            *(float2*)(cO1 + r0 * 66 + cc)       = make_float2(O1[nd][0], O1[nd][1]);
            *(float2*)(cO1 + (r0 + 8) * 66 + cc) = make_float2(O1[nd][2], O1[nd][3]);
            *(float2*)(cO2 + r0 * 66 + cc)       = make_float2(O2[nd][0], O2[nd][1]);
            *(float2*)(cO2 + (r0 + 8) * 66 + cc) = make_float2(O2[nd][2], O2[nd][3]);
        }
        if ((lane & 3) == 0) {
            sl1[r0] = L1a; sl1[r0 + 8] = L1b;
            sl2[r0] = L2a; sl2[r0 + 8] = L2b;
        }
    }
    __syncthreads();
    if (half == 0) {
        const float i1a = 1.0f / (L1a + sl1[r0]);
        const float i1b = 1.0f / (L1b + sl1[r0 + 8]);
        const float i2a = lam  / (L2a + sl2[r0]);
        const float i2b = lam  / (L2b + sl2[r0 + 8]);
        #pragma unroll
        for (int nd = 0; nd < 8; nd++) {
            int cc = nd * 8 + (lane & 3) * 2;
            float2 o1h = *(float2*)(cO1 + r0 * 66 + cc);
            float2 o1g = *(float2*)(cO1 + (r0 + 8) * 66 + cc);
            float2 o2h = *(float2*)(cO2 + r0 * 66 + cc);
            float2 o2g = *(float2*)(cO2 + (r0 + 8) * 66 + cc);
            float2 v0 = make_float2((O1[nd][0] + o1h.x) * i1a - (O2[nd][0] + o2h.x) * i2a,
                                    (O1[nd][1] + o1h.y) * i1a - (O2[nd][1] + o2h.y) * i2a);
            float2 v1 = make_float2((O1[nd][2] + o1g.x) * i1b - (O2[nd][2] + o2g.x) * i2b,
                                    (O1[nd][3] + o1g.y) * i1b - (O2[nd][3] + o2g.y) * i2b);
            int s0 = q0 + r0, s1r = s0 + 8;
            *(float2*)(g_attn + (size_t)((b * Sc + s0)  * Hc + h) * Dc + cc) = v0;
            *(float2*)(g_attn + (size_t)((b * Sc + s1r) * Hc + h) * Dc + cc) = v1;
        }
    }
}

// ============================================================
// Group statistics (unchanged)
// ============================================================
__global__ __launch_bounds__(256)
void stats_kernel()
{
    const int b = blockIdx.x >> 3;
    const int j = blockIdx.x & 7;
    const int tid = threadIdx.x;
    double s = 0.0, sq = 0.0;
    const float* base = g_attn + (size_t)b*Sc*Hc*Dc + j*8;
    for (int t = tid; t < Sc*Hc; t += 256) {
        const float* p = base + (size_t)t * 64;
        #pragma unroll
        for (int i = 0; i < 8; i++) {
            float x = p[i];
            s  += (double)x;
            sq += (double)x * (double)x;
        }
    }
    __shared__ double ss[256], sqq[256];
    ss[tid] = s; sqq[tid] = sq;
    __syncthreads();
    for (int o = 128; o > 0; o >>= 1) {
        if (tid < o) { ss[tid] += ss[tid+o]; sqq[tid] += sqq[tid+o]; }
        __syncthreads();
    }
    if (tid == 0) {
        double mean = ss[0] / 65536.0;
        double var  = sqq[0] / 65536.0 - mean * mean;
        g_mean[blockIdx.x] = (float)mean;
        g_rstd[blockIdx.x] = (float)(1.0 / sqrt(var + 1e-3));
    }
}

// ============================================================
// Final elementwise (unchanged)
// ============================================================
__global__ __launch_bounds__(256)
void final_kernel(const float* __restrict__ gamma, const float* __restrict__ beta,
                  const float* __restrict__ li_p, float* __restrict__ out)
{
    const int idx = (blockIdx.x * 256 + threadIdx.x) * 4;
    const int d = idx & 63;
    const int h = (idx >> 6) & 7;
    const int s = (idx >> 9) & 1023;
    const int b = idx >> 19;
    const int j = d >> 3;
    const float mean = g_mean[b*8+j];
    const float rstd = g_rstd[b*8+j];
    const float li = 1.0f - li_p[0];
    float4 a  = *(const float4*)(g_attn + idx);
    float4 g  = *(const float4*)(g_gate + (size_t)((b*Hc+h)*Sc + s)*Dc + d);
    float4 gm = *(const float4*)(gamma + d);
    float4 bt = *(const float4*)(beta + d);
    float4 o;
    o.x = ((a.x-mean)*rstd*gm.x + bt.x) * li * (1.0f/(1.0f+__expf(-g.x)));
    o.y = ((a.y-mean)*rstd*gm.y + bt.y) * li * (1.0f/(1.0f+__expf(-g.y)));
    o.z = ((a.z-mean)*rstd*gm.z + bt.z) * li * (1.0f/(1.0f+__expf(-g.z)));
    o.w = ((a.w-mean)*rstd*gm.w + bt.w) * li * (1.0f/(1.0f+__expf(-g.w)));
    *(float4*)(out + idx) = o;
}

// ============================================================
extern "C" void kernel_launch(void* const* d_in, const int* in_sizes, int n_in,
                              void* d_out, int out_size)
{
    const float* query  = (const float*)d_in[0];
    const float* key    = (const float*)d_in[1];
    const float* values = (const float*)d_in[2];
    const float* Wq = (const float*)d_in[3];
    const float* bq = (const float*)d_in[4];
    const float* Wk = (const float*)d_in[5];
    const float* bk = (const float*)d_in[6];
    const float* Wv = (const float*)d_in[7];
    const float* bv = (const float*)d_in[8];
    const float* gamma = (const float*)d_in[9];
    const float* beta  = (const float*)d_in[10];
    const float* lam   = (const float*)d_in[11];
    const float* lambda_init = (const float*)d_in[12];
    float* out = (float*)d_out;

    cudaFuncSetAttribute(gemm_hmma, cudaFuncAttributeMaxDynamicSharedMemorySize, GEMM_SMEM);
    cudaFuncSetAttribute(attn_hmma, cudaFuncAttributeMaxDynamicSharedMemorySize, ATTN_SMEM);

    convA_all<<<12288, 256>>>(query, key, values);
    convW_all<<<dim3(16, 96), 256>>>(Wq, Wk, Wv);

    gemm_hmma<<<dim3(64, 24), 256, GEMM_SMEM>>>(bq, bk, bv);

    attn_hmma<<<dim3(16, 8, 8), 256, ATTN_SMEM>>>(lam);

    stats_kernel<<<64, 256>>>();
    final_kernel<<<NTOT/1024, 256>>>(gamma, beta, lambda_init, out);
}

// round 15
// speedup vs baseline: 1.0544x; 1.0544x over previous
#include <cuda_runtime.h>
#include <cuda_bf16.h>
#include <math.h>
#include <stdint.h>

#define Bc 8
#define Sc 1024
#define Hc 8
#define Dc 64
#define DMc 512
#define NTOT (Bc*Hc*Sc*Dc)   // 4,194,304

// ---- scratch (device globals; no allocations allowed) ----
__device__ float g_gate[NTOT];   // (B,H,S,D) fp32
__device__ float g_attn[NTOT];   // (B,S,H,D) fp32
__device__ float g_mean[Bc*8];
__device__ float g_rstd[Bc*8];

// bf16 hi/lo attention operands, (B,H,S,D)
__device__ __align__(16) __nv_bfloat16 g_q1h[NTOT], g_q1l[NTOT];
__device__ __align__(16) __nv_bfloat16 g_q2h[NTOT], g_q2l[NTOT];
__device__ __align__(16) __nv_bfloat16 g_k1h[NTOT], g_k1l[NTOT];
__device__ __align__(16) __nv_bfloat16 g_k2h[NTOT], g_k2l[NTOT];
__device__ __align__(16) __nv_bfloat16 g_vh[NTOT],  g_vl[NTOT];

// bf16 hi/lo split operands for tensor-core projection GEMMs
__device__ __align__(16) __nv_bfloat16 g_Ahi[3][8192*512];
__device__ __align__(16) __nv_bfloat16 g_Alo[3][8192*512];
__device__ __align__(16) __nv_bfloat16 g_Whi[3072*512];   // W^T, [N][K] layout
__device__ __align__(16) __nv_bfloat16 g_Wlo[3072*512];

// ============================================================
// helpers
// ============================================================
__device__ __forceinline__ uint32_t smem_u32(const void* p) {
    uint32_t a;
    asm("{ .reg .u64 t; cvta.to.shared.u64 t, %1; cvt.u32.u64 %0, t; }" : "=r"(a) : "l"(p));
    return a;
}
__device__ __forceinline__ void ldsm_x4(uint32_t* r, uint32_t addr) {
    asm volatile("ldmatrix.sync.aligned.m8n8.x4.shared.b16 {%0,%1,%2,%3}, [%4];"
                 : "=r"(r[0]), "=r"(r[1]), "=r"(r[2]), "=r"(r[3]) : "r"(addr));
}
__device__ __forceinline__ void ldsm_x4t(uint32_t* r, uint32_t addr) {
    asm volatile("ldmatrix.sync.aligned.m8n8.x4.trans.shared.b16 {%0,%1,%2,%3}, [%4];"
                 : "=r"(r[0]), "=r"(r[1]), "=r"(r[2]), "=r"(r[3]) : "r"(addr));
}
__device__ __forceinline__ void mma16816(float* c, const uint32_t* a, const uint32_t* b) {
    asm volatile("mma.sync.aligned.m16n8k16.row.col.f32.bf16.bf16.f32 "
                 "{%0,%1,%2,%3}, {%4,%5,%6,%7}, {%8,%9}, {%0,%1,%2,%3};"
                 : "+f"(c[0]), "+f"(c[1]), "+f"(c[2]), "+f"(c[3])
                 : "r"(a[0]), "r"(a[1]), "r"(a[2]), "r"(a[3]), "r"(b[0]), "r"(b[1]));
}
__device__ __forceinline__ void cp_async16(uint32_t sa, const void* g) {
    asm volatile("cp.async.cg.shared.global [%0], [%1], 16;" :: "r"(sa), "l"(g) : "memory");
}
__device__ __forceinline__ uint32_t cvt2bf(float a, float b) {
    uint32_t r;
    asm("cvt.rn.bf16x2.f32 %0, %1, %2;" : "=r"(r) : "f"(b), "f"(a));
    return r;
}
__device__ __forceinline__ void split2bf(float a, float b, uint32_t& ph, uint32_t& pl) {
    ph = cvt2bf(a, b);
    float ha = __uint_as_float(ph << 16);
    float hb = __uint_as_float(ph & 0xFFFF0000u);
    pl = cvt2bf(a - ha, b - hb);
}
#define SW128(off) ((off) ^ (((off) >> 3) & 0x70))
#define SC2G 0.18033688011112042f   // 0.125 * log2(e)

// ============================================================
// Fused conversion kernels
// ============================================================
__global__ __launch_bounds__(256)
void convA_all(const float* __restrict__ Xq, const float* __restrict__ Xk,
               const float* __restrict__ Xv)
{
    const int which = blockIdx.x >> 12;
    const float* X = (which == 0) ? Xq : (which == 1) ? Xk : Xv;
    int i = ((blockIdx.x & 4095) * 256 + threadIdx.x) * 4;
    float4 x = *(const float4*)(X + i);
    uint32_t h01, l01, h23, l23;
    split2bf(x.x, x.y, h01, l01);
    split2bf(x.z, x.w, h23, l23);
    uint2* ph = (uint2*)(&g_Ahi[which][i]);
    uint2* pl = (uint2*)(&g_Alo[which][i]);
    *ph = make_uint2(h01, h23);
    *pl = make_uint2(l01, l23);
}

__global__ __launch_bounds__(256)
void convW_all(const float* __restrict__ Wq, const float* __restrict__ Wk,
               const float* __restrict__ Wv)
{
    __shared__ float t[32][33];
    int by = blockIdx.y;
    const float* W; int N; int off;
    if (by < 48)      { W = Wq; N = 1536; off = 0;           }
    else if (by < 80) { W = Wk; N = 1024; off = 1536*512; by -= 48; }
    else              { W = Wv; N = 512;  off = 2560*512; by -= 80; }
    const int k0 = blockIdx.x * 32;
    const int n0 = by * 32;
    const int tx = threadIdx.x & 31;
    const int ty = threadIdx.x >> 5;
    #pragma unroll
    for (int i = ty; i < 32; i += 8)
        t[i][tx] = W[(size_t)(k0 + i) * N + n0 + tx];
    __syncthreads();
    #pragma unroll
    for (int i = ty; i < 32; i += 8) {
        float x = t[tx][i];
        __nv_bfloat16 h = __float2bfloat16(x);
        size_t idx = (size_t)off + (size_t)(n0 + i) * 512 + k0 + tx;
        g_Whi[idx] = h;
        g_Wlo[idx] = __float2bfloat16(x - __bfloat162float(h));
    }
}

// ============================================================
// Merged HMMA projection GEMM — exact R13 (2-stage) version.
// q1/q2 pre-scaled by 0.125*log2e.
// ============================================================
#define GEMM_SMEM 65536

__global__ __launch_bounds__(256, 2)
void gemm_hmma(const float* __restrict__ bq, const float* __restrict__ bk,
               const float* __restrict__ bv)
{
    extern __shared__ __align__(1024) char smem[];
    const uint32_t sbase = smem_u32(smem);
    const int tid = threadIdx.x;
    const int lane = tid & 31;
    const int wid = tid >> 5;
    const int wm = (wid & 1) * 64;
    const int wn = (wid >> 1) * 32;

    const int m0 = blockIdx.x * 128;
    int by = blockIdx.y;
    int which, woff, perHead, mode; const float* bias;
    if (by < 12)      { which = 0; woff = 0;        bias = bq; perHead = 192; mode = 0; }
    else if (by < 20) { which = 1; woff = 1536*512; bias = bk; perHead = 128; mode = 1; by -= 12; }
    else              { which = 2; woff = 2560*512; bias = bv; perHead = 64;  mode = 2; by -= 20; }
    const int n0 = by * 128;

    const __nv_bfloat16* Ahi = g_Ahi[which];
    const __nv_bfloat16* Alo = g_Alo[which];
    const __nv_bfloat16* Whi = g_Whi + (size_t)woff;
    const __nv_bfloat16* Wlo = g_Wlo + (size_t)woff;

    float C[4][4][4];
    #pragma unroll
    for (int i = 0; i < 4; i++)
        #pragma unroll
        for (int j = 0; j < 4; j++)
            #pragma unroll
            for (int c = 0; c < 4; c++) C[i][j][c] = 0.0f;

    const int lrow = tid >> 1;
    const int lu   = (tid & 1) * 2;
    auto load_chunk = [&](int c, int s) {
        const int kc = c * 32;
        const uint32_t ab = (uint32_t)s * 32768u;
        const uint32_t bb = ab + 16384u;
        #pragma unroll
        for (int e = 0; e < 2; e++) {
            int u = lu + e;
            uint32_t dh = SW128((uint32_t)(lrow * 128 + u * 16));
            uint32_t dl = SW128((uint32_t)(lrow * 128 + 64 + u * 16));
            cp_async16(sbase + ab + dh, Ahi + (size_t)(m0 + lrow) * 512 + kc + u * 8);
            cp_async16(sbase + ab + dl, Alo + (size_t)(m0 + lrow) * 512 + kc + u * 8);
            cp_async16(sbase + bb + dh, Whi + (size_t)(n0 + lrow) * 512 + kc + u * 8);
            cp_async16(sbase + bb + dl, Wlo + (size_t)(n0 + lrow) * 512 + kc + u * 8);
        }
        asm volatile("cp.async.commit_group;" ::: "memory");
    };

    load_chunk(0, 0);

    for (int c = 0; c < 16; c++) {
        if (c < 15) load_chunk(c + 1, (c + 1) & 1);
        if (c < 15) asm volatile("cp.async.wait_group 1;" ::: "memory");
        else        asm volatile("cp.async.wait_group 0;" ::: "memory");
        __syncthreads();

        const uint32_t ab = (uint32_t)(c & 1) * 32768u;
        const uint32_t bb = ab + 16384u;
        #pragma unroll
        for (int ks = 0; ks < 2; ks++) {
            uint32_t ah[4][4], al[4][4];
            #pragma unroll
            for (int mi = 0; mi < 4; mi++) {
                uint32_t base = (uint32_t)((wm + mi * 16 + (lane & 15)) * 128 + ks * 32 + (lane >> 4) * 16);
                ldsm_x4(ah[mi], sbase + ab + SW128(base));
                ldsm_x4(al[mi], sbase + ab + SW128(base + 64));
            }
            uint32_t bh[2][4], bl[2][4];
            #pragma unroll
            for (int n2 = 0; n2 < 2; n2++) {
                uint32_t base = (uint32_t)((wn + n2 * 16 + ((lane >> 4) & 1) * 8 + (lane & 7)) * 128
                                           + ks * 32 + ((lane >> 3) & 1) * 16);
                ldsm_x4(bh[n2], sbase + bb + SW128(base));
                ldsm_x4(bl[n2], sbase + bb + SW128(base + 64));
            }
            #pragma unroll
            for (int mi = 0; mi < 4; mi++)
                #pragma unroll
                for (int n2 = 0; n2 < 2; n2++)
                    #pragma unroll
                    for (int e = 0; e < 2; e++) {
                        mma16816(C[mi][2*n2+e], ah[mi], bh[n2] + 2*e);
                        mma16816(C[mi][2*n2+e], ah[mi], bl[n2] + 2*e);
                        mma16816(C[mi][2*n2+e], al[mi], bh[n2] + 2*e);
                    }
        }
        __syncthreads();
    }

    #pragma unroll
    for (int ni = 0; ni < 4; ni++) {
        const int ng = n0 + wn + ni * 8 + (lane & 3) * 2;
        const int hh  = ng / perHead;
        const int r   = ng % perHead;
        const int seg = r >> 6;
        const int d   = r & 63;
        const float bx = bias[ng], by2 = bias[ng + 1];
        __nv_bfloat16 *ph = 0, *pl = 0; float* pf = 0;
        if (mode == 0) {
            if (seg == 0)      { ph = g_q1h; pl = g_q1l; }
            else if (seg == 1) { ph = g_q2h; pl = g_q2l; }
            else               { pf = g_gate; }
        } else if (mode == 1) {
            if (seg == 0) { ph = g_k1h; pl = g_k1l; }
            else          { ph = g_k2h; pl = g_k2l; }
        } else { ph = g_vh; pl = g_vl; }
        const float qs = (mode == 0 && seg != 2) ? SC2G : 1.0f;
        #pragma unroll
        for (int mi = 0; mi < 4; mi++) {
            #pragma unroll
            for (int half = 0; half < 2; half++) {
                int m = m0 + wm + mi * 16 + (lane >> 2) + half * 8;
                int bb2 = m >> 10, s = m & 1023;
                size_t idx = (size_t)((bb2 * Hc + hh) * Sc + s) * Dc + d;
                float v0 = (C[mi][ni][half * 2 + 0] + bx)  * qs;
                float v1 = (C[mi][ni][half * 2 + 1] + by2) * qs;
                if (pf) {
                    *(float2*)(pf + idx) = make_float2(v0, v1);
                } else {
                    uint32_t hp, lp;
                    split2bf(v0, v1, hp, lp);
                    *(uint32_t*)(ph + idx) = hp;
                    *(uint32_t*)(pl + idx) = lp;
                }
            }
        }
    }
}

// ============================================================
// HMMA flash attention v8: branch-split warps (warp = rowblock
// x branch), Q fragments HOISTED out of the kt loop (loop-
// invariant; 32 regs), O shrinks to one branch (32 regs).
// LDSM/iter: 40 -> 32. Full rows per warp -> no split-KV merge;
// single branch combine at end.
// ============================================================
#define AQ1H 0
#define AQ1L 8192
#define AQ2H 16384
#define AQ2L 24576
#define AKV0 32768
#define KVSZ 24576     // per stage: k1h@0 k1l@4096 k2h@8192 k2l@12288 vh@16384 vl@20480
#define AML  81920     // l2 exchange: 128 fp32
#define ACMB 32768     // O2 exchange: 64x66 fp32 (overlaps KV after loop)
#define ATTN_SMEM 83968

__global__ __launch_bounds__(256, 2)
void attn_hmma(const float* __restrict__ lam_p)
{
    extern __shared__ __align__(1024) char smem[];
    const uint32_t sb = smem_u32(smem);
    const int tid = threadIdx.x;
    const int lane = tid & 31;
    const int w = tid >> 5;
    const int wm = (w & 3) * 16;       // row block
    const int br = w >> 2;             // branch (0 or 1)

    const int q0 = blockIdx.x * 64;
    const int h = blockIdx.y;
    const int b = blockIdx.z;
    const size_t ho = (size_t)(b * Hc + h) * Sc * Dc;

    const __nv_bfloat16* src[6] = { g_k1h + ho, g_k1l + ho, g_k2h + ho,
                                    g_k2l + ho, g_vh + ho, g_vl + ho };

    // load Q tiles (4 x 64x64 bf16, swizzled)
    {
        const __nv_bfloat16* qs[4] = { g_q1h + ho + (size_t)q0 * Dc, g_q1l + ho + (size_t)q0 * Dc,
                                       g_q2h + ho + (size_t)q0 * Dc, g_q2l + ho + (size_t)q0 * Dc };
        #pragma unroll
        for (int t = 0; t < 4; t++)
            #pragma unroll
            for (int i = 0; i < 2; i++) {
                int idx = tid + 256 * i;
                int row = idx >> 3, u = idx & 7;
                *(uint4*)(smem + t * 8192 + SW128((uint32_t)(row * 128 + u * 16))) =
                    *(const uint4*)(qs[t] + row * 64 + u * 8);
            }
    }
    // prologue: KV tile 0 into stage 0
    {
        int row = tid >> 3, u = tid & 7;
        uint32_t soff = SW128((uint32_t)(row * 128 + u * 16));
        #pragma unroll
        for (int t = 0; t < 6; t++)
            cp_async16(sb + AKV0 + t * 4096 + soff, src[t] + (size_t)row * 64 + u * 8);
        asm volatile("cp.async.commit_group;" ::: "memory");
    }
    __syncthreads();   // Q smem visible for the hoisted fragment loads

    // ---- hoist loop-invariant Q fragments for this warp's branch ----
    uint32_t qh[4][4], ql[4][4];
    {
        const uint32_t QHo = br ? (uint32_t)AQ2H : (uint32_t)AQ1H;
        #pragma unroll
        for (int ks = 0; ks < 4; ks++) {
            uint32_t aoff = SW128((uint32_t)((wm + (lane & 15)) * 128 + ks * 32 + (lane >> 4) * 16));
            ldsm_x4(qh[ks], sb + QHo + aoff);
            ldsm_x4(ql[ks], sb + QHo + 8192u + aoff);
        }
    }

    float O[8][4];
    #pragma unroll
    for (int nd = 0; nd < 8; nd++)
        #pragma unroll
        for (int c = 0; c < 4; c++) O[nd][c] = 0.0f;
    float La = 0.0f, Lb = 0.0f;

    const int r0 = wm + (lane >> 2);
    const uint32_t KHo = (uint32_t)br * 8192u;   // k1 @0, k2 @8192 (hi); lo at +4096

    for (int kt = 0; kt < 32; kt++) {
        const uint32_t bufb = AKV0 + (uint32_t)(kt & 1) * KVSZ;
        asm volatile("cp.async.wait_group 0;" ::: "memory");
        __syncthreads();

        // ---- QK^T: 16 rows x full 32 keys, one branch (3-term EC) ----
        float s[4][4];
        #pragma unroll
        for (int ni = 0; ni < 4; ni++)
            #pragma unroll
            for (int c = 0; c < 4; c++) s[ni][c] = 0.0f;

        #pragma unroll
        for (int ks = 0; ks < 4; ks++) {
            uint32_t bh[2][4], bl[2][4];
            #pragma unroll
            for (int n2 = 0; n2 < 2; n2++) {
                uint32_t brow = (uint32_t)(n2 * 16 + ((lane >> 4) & 1) * 8 + (lane & 7));
                uint32_t boff = SW128(brow * 128 + (uint32_t)(ks * 32 + ((lane >> 3) & 1) * 16));
                ldsm_x4(bh[n2], sb + bufb + KHo + boff);
                ldsm_x4(bl[n2], sb + bufb + KHo + 4096u + boff);
            }
            #pragma unroll
            for (int n2 = 0; n2 < 2; n2++)
                #pragma unroll
                for (int e = 0; e < 2; e++) {
                    mma16816(s[2*n2+e], qh[ks], bh[n2] + 2*e);
                    mma16816(s[2*n2+e], qh[ks], bl[n2] + 2*e);
                    mma16816(s[2*n2+e], ql[ks], bh[n2] + 2*e);
                }
        }

        // prefetch next 32-key tile
        if (kt < 31) {
            const uint32_t nb = AKV0 + (uint32_t)((kt + 1) & 1) * KVSZ;
            int row = tid >> 3, u = tid & 7;
            uint32_t soff = SW128((uint32_t)(row * 128 + u * 16));
            #pragma unroll
            for (int t = 0; t < 6; t++)
                cp_async16(sb + nb + t * 4096 + soff,
                           src[t] + (size_t)((kt + 1) * 32 + row) * 64 + u * 8);
            asm volatile("cp.async.commit_group;" ::: "memory");
        }

        // ---- exp2 on fragments, pack into PV A-frags (2 ksteps) ----
        uint32_t ph[2][4], pl_[2][4];
        #pragma unroll
        for (int j = 0; j < 2; j++) {
            #pragma unroll
            for (int e = 0; e < 2; e++) {
                const int ni = 2 * j + e;
                float q0v = exp2f(s[ni][0]);
                float q1v = exp2f(s[ni][1]);
                float q2v = exp2f(s[ni][2]);
                float q3v = exp2f(s[ni][3]);
                La += q0v + q1v; Lb += q2v + q3v;
                split2bf(q0v, q1v, ph[j][2 * e],     pl_[j][2 * e]);
                split2bf(q2v, q3v, ph[j][2 * e + 1], pl_[j][2 * e + 1]);
            }
        }

        // ---- O += P V over full 32-key tile (2 ksteps) ----
        #pragma unroll
        for (int j = 0; j < 2; j++) {
            #pragma unroll
            for (int np = 0; np < 4; np++) {
                uint32_t voff = SW128((uint32_t)((j * 16 + (lane & 15)) * 128 +
                                                 (np * 2 + ((lane >> 4) & 1)) * 16));
                uint32_t vh4[4], vl4[4];
                ldsm_x4t(vh4, sb + bufb + 16384u + voff);
                ldsm_x4t(vl4, sb + bufb + 20480u + voff);
                #pragma unroll
                for (int e = 0; e < 2; e++) {
                    mma16816(O[2*np+e], ph[j], vh4 + 2*e);
                    mma16816(O[2*np+e], ph[j], vl4 + 2*e);
                    mma16816(O[2*np+e], pl_[j], vh4 + 2*e);
                }
            }
        }
    }

    // reduce l over the quad (rows complete per warp)
    La += __shfl_xor_sync(0xffffffffu, La, 1);
    La += __shfl_xor_sync(0xffffffffu, La, 2);
    Lb += __shfl_xor_sync(0xffffffffu, Lb, 1);
    Lb += __shfl_xor_sync(0xffffffffu, Lb, 2);
    __syncthreads();

    // ---- branch combine: G = O1/l1 - lam*O2/l2 ----
    float* cO = (float*)(smem + ACMB);   // [64][66] branch-2 O
    float* sl = (float*)(smem + AML);    // branch-2 l per row (128)
    const float lam = lam_p[0];

    if (br == 1) {
        #pragma unroll
        for (int nd = 0; nd < 8; nd++) {
            int cc = nd * 8 + (lane & 3) * 2;
            *(float2*)(cO + r0 * 66 + cc)       = make_float2(O[nd][0], O[nd][1]);
            *(float2*)(cO + (r0 + 8) * 66 + cc) = make_float2(O[nd][2], O[nd][3]);
        }
        if ((lane & 3) == 0) {
            sl[r0] = La; sl[r0 + 8] = Lb;
        }
    }
    __syncthreads();
    if (br == 0) {
        const float i1a = 1.0f / La;
        const float i1b = 1.0f / Lb;
        const float i2a = lam  / sl[r0];
        const float i2b = lam  / sl[r0 + 8];
        #pragma unroll
        for (int nd = 0; nd < 8; nd++) {
            int cc = nd * 8 + (lane & 3) * 2;
            float2 o2h = *(float2*)(cO + r0 * 66 + cc);
            float2 o2g = *(float2*)(cO + (r0 + 8) * 66 + cc);
            float2 v0 = make_float2(O[nd][0] * i1a - o2h.x * i2a,
                                    O[nd][1] * i1a - o2h.y * i2a);
            float2 v1 = make_float2(O[nd][2] * i1b - o2g.x * i2b,
                                    O[nd][3] * i1b - o2g.y * i2b);
            int s0 = q0 + r0, s1r = s0 + 8;
            *(float2*)(g_attn + (size_t)((b * Sc + s0)  * Hc + h) * Dc + cc) = v0;
            *(float2*)(g_attn + (size_t)((b * Sc + s1r) * Hc + h) * Dc + cc) = v1;
        }
    }
}

// ============================================================
// Group statistics (unchanged)
// ============================================================
__global__ __launch_bounds__(256)
void stats_kernel()
{
    const int b = blockIdx.x >> 3;
    const int j = blockIdx.x & 7;
    const int tid = threadIdx.x;
    double s = 0.0, sq = 0.0;
    const float* base = g_attn + (size_t)b*Sc*Hc*Dc + j*8;
    for (int t = tid; t < Sc*Hc; t += 256) {
        const float* p = base + (size_t)t * 64;
        #pragma unroll
        for (int i = 0; i < 8; i++) {
            float x = p[i];
            s  += (double)x;
            sq += (double)x * (double)x;
        }
    }
    __shared__ double ss[256], sqq[256];
    ss[tid] = s; sqq[tid] = sq;
    __syncthreads();
    for (int o = 128; o > 0; o >>= 1) {
        if (tid < o) { ss[tid] += ss[tid+o]; sqq[tid] += sqq[tid+o]; }
        __syncthreads();
    }
    if (tid == 0) {
        double mean = ss[0] / 65536.0;
        double var  = sqq[0] / 65536.0 - mean * mean;
        g_mean[blockIdx.x] = (float)mean;
        g_rstd[blockIdx.x] = (float)(1.0 / sqrt(var + 1e-3));
    }
}

// ============================================================
// Final elementwise (unchanged)
// ============================================================
__global__ __launch_bounds__(256)
void final_kernel(const float* __restrict__ gamma, const float* __restrict__ beta,
                  const float* __restrict__ li_p, float* __restrict__ out)
{
    const int idx = (blockIdx.x * 256 + threadIdx.x) * 4;
    const int d = idx & 63;
    const int h = (idx >> 6) & 7;
    const int s = (idx >> 9) & 1023;
    const int b = idx >> 19;
    const int j = d >> 3;
    const float mean = g_mean[b*8+j];
    const float rstd = g_rstd[b*8+j];
    const float li = 1.0f - li_p[0];
    float4 a  = *(const float4*)(g_attn + idx);
    float4 g  = *(const float4*)(g_gate + (size_t)((b*Hc+h)*Sc + s)*Dc + d);
    float4 gm = *(const float4*)(gamma + d);
    float4 bt = *(const float4*)(beta + d);
    float4 o;
    o.x = ((a.x-mean)*rstd*gm.x + bt.x) * li * (1.0f/(1.0f+__expf(-g.x)));
    o.y = ((a.y-mean)*rstd*gm.y + bt.y) * li * (1.0f/(1.0f+__expf(-g.y)));
    o.z = ((a.z-mean)*rstd*gm.z + bt.z) * li * (1.0f/(1.0f+__expf(-g.z)));
    o.w = ((a.w-mean)*rstd*gm.w + bt.w) * li * (1.0f/(1.0f+__expf(-g.w)));
    *(float4*)(out + idx) = o;
}

// ============================================================
extern "C" void kernel_launch(void* const* d_in, const int* in_sizes, int n_in,
                              void* d_out, int out_size)
{
    const float* query  = (const float*)d_in[0];
    const float* key    = (const float*)d_in[1];
    const float* values = (const float*)d_in[2];
    const float* Wq = (const float*)d_in[3];
    const float* bq = (const float*)d_in[4];
    const float* Wk = (const float*)d_in[5];
    const float* bk = (const float*)d_in[6];
    const float* Wv = (const float*)d_in[7];
    const float* bv = (const float*)d_in[8];
    const float* gamma = (const float*)d_in[9];
    const float* beta  = (const float*)d_in[10];
    const float* lam   = (const float*)d_in[11];
    const float* lambda_init = (const float*)d_in[12];
    float* out = (float*)d_out;

    cudaFuncSetAttribute(gemm_hmma, cudaFuncAttributeMaxDynamicSharedMemorySize, GEMM_SMEM);
    cudaFuncSetAttribute(attn_hmma, cudaFuncAttributeMaxDynamicSharedMemorySize, ATTN_SMEM);

    convA_all<<<12288, 256>>>(query, key, values);
    convW_all<<<dim3(16, 96), 256>>>(Wq, Wk, Wv);

    gemm_hmma<<<dim3(64, 24), 256, GEMM_SMEM>>>(bq, bk, bv);

    attn_hmma<<<dim3(16, 8, 8), 256, ATTN_SMEM>>>(lam);

    stats_kernel<<<64, 256>>>();
    final_kernel<<<NTOT/1024, 256>>>(gamma, beta, lambda_init, out);
}